// round 1
// baseline (speedup 1.0000x reference)
#include <cuda_runtime.h>
#include <math.h>

// Problem constants
#define M_BATCH   8192
#define N_NODES   1023
#define N_PAD     1024
#define K_DIM     1024
#define N_CLASSES 10
#define N_LEAVES  1024

// Scratch (allocation-free rule: __device__ globals)
__device__ float g_probs[(size_t)M_BATCH * N_PAD];   // sigmoid outputs, [m][n] layout
__device__ float g_leaf_reward[N_LEAVES];

// ---------------------------------------------------------------------------
// Kernel 1: leaf_reward[l] = softmax(leaf_dist[l,:]) . class_reward
// ---------------------------------------------------------------------------
__global__ void leaf_reward_kernel(const float* __restrict__ leaf_dist,
                                   const float* __restrict__ class_reward) {
    int l = blockIdx.x * blockDim.x + threadIdx.x;
    if (l >= N_LEAVES) return;
    float v[N_CLASSES];
    float mx = -1e30f;
#pragma unroll
    for (int c = 0; c < N_CLASSES; c++) {
        v[c] = leaf_dist[l * N_CLASSES + c];
        mx = fmaxf(mx, v[c]);
    }
    float s = 0.f;
#pragma unroll
    for (int c = 0; c < N_CLASSES; c++) {
        v[c] = expf(v[c] - mx);
        s += v[c];
    }
    float inv = 1.f / s;
    float r = 0.f;
#pragma unroll
    for (int c = 0; c < N_CLASSES; c++) r += v[c] * inv * class_reward[c];
    g_leaf_reward[l] = r;
}

// ---------------------------------------------------------------------------
// Kernel 2: tiled SGEMM (logits = x @ W^T) fused with sigmoid(beta*(z+b))
//   BM=128, BN=64, BK=16, 256 threads, each thread -> 8 (m) x 4 (n) outputs.
//   Thread n-columns are strided (n = tx + 16*j) so epilogue stores coalesce.
// ---------------------------------------------------------------------------
#define BM 128
#define BN 64
#define BK 16
#define TM 8
#define TN 4

__global__ __launch_bounds__(256, 2)
void gemm_sigmoid_kernel(const float* __restrict__ x,
                         const float* __restrict__ W,
                         const float* __restrict__ bvec,
                         const float* __restrict__ beta) {
    __shared__ float As[BK][BM];   // As[k][m]
    __shared__ float Bs[BK][BN];   // Bs[k][n]

    const int tid = threadIdx.x;
    const int tx  = tid & 15;      // n sub-index (0..15)
    const int ty  = tid >> 4;      // m sub-index (0..15)
    const int m0  = blockIdx.y * BM;
    const int n0  = blockIdx.x * BN;

    float acc[TM][TN];
#pragma unroll
    for (int i = 0; i < TM; i++)
#pragma unroll
        for (int j = 0; j < TN; j++) acc[i][j] = 0.f;

    for (int k0 = 0; k0 < K_DIM; k0 += BK) {
        // ---- load A tile: x[m0..m0+127][k0..k0+15]  (512 float4s, 2/thread)
#pragma unroll
        for (int u = 0; u < 2; u++) {
            int idx = tid + u * 256;
            int row = idx >> 2;           // 0..127
            int c4  = (idx & 3) * 4;      // 0,4,8,12
            float4 v = *reinterpret_cast<const float4*>(
                &x[(size_t)(m0 + row) * K_DIM + k0 + c4]);
            As[c4 + 0][row] = v.x;
            As[c4 + 1][row] = v.y;
            As[c4 + 2][row] = v.z;
            As[c4 + 3][row] = v.w;
        }
        // ---- load B tile: W[n0..n0+63][k0..k0+15] -> Bs[k][n] (transposed)
        {
            int row = tid >> 2;           // 0..63 (n within tile)
            int c4  = (tid & 3) * 4;      // 0,4,8,12
            int n   = n0 + row;
            float4 v = make_float4(0.f, 0.f, 0.f, 0.f);
            if (n < N_NODES)
                v = *reinterpret_cast<const float4*>(
                    &W[(size_t)n * K_DIM + k0 + c4]);
            Bs[c4 + 0][row] = v.x;
            Bs[c4 + 1][row] = v.y;
            Bs[c4 + 2][row] = v.z;
            Bs[c4 + 3][row] = v.w;
        }
        __syncthreads();

#pragma unroll
        for (int k = 0; k < BK; k++) {
            float a[TM], bb[TN];
            float4 a0 = *reinterpret_cast<const float4*>(&As[k][ty * TM]);
            float4 a1 = *reinterpret_cast<const float4*>(&As[k][ty * TM + 4]);
            a[0] = a0.x; a[1] = a0.y; a[2] = a0.z; a[3] = a0.w;
            a[4] = a1.x; a[5] = a1.y; a[6] = a1.z; a[7] = a1.w;
#pragma unroll
            for (int j = 0; j < TN; j++) bb[j] = Bs[k][tx + 16 * j];
#pragma unroll
            for (int i = 0; i < TM; i++)
#pragma unroll
                for (int j = 0; j < TN; j++)
                    acc[i][j] = fmaf(a[i], bb[j], acc[i][j]);
        }
        __syncthreads();
    }

    // ---- epilogue: sigmoid(beta*(z+b)), coalesced stores to g_probs[m][n]
#pragma unroll
    for (int j = 0; j < TN; j++) {
        int n = n0 + tx + 16 * j;
        if (n >= N_NODES) continue;
        float bn  = bvec[n];
        float btn = beta[n];
#pragma unroll
        for (int i = 0; i < TM; i++) {
            int m = m0 + ty * TM + i;
            float z = btn * (acc[i][j] + bn);
            g_probs[(size_t)m * N_PAD + n] = 1.f / (1.f + __expf(-z));
        }
    }
}

// ---------------------------------------------------------------------------
// Kernel 3: per-row bottom-up tree fold.
//   V[node] = p*V[2node+1] + (1-p)*V[2node+2]; loss = V[0].
//   Level-by-level in shared memory with ping-pong buffers.
// ---------------------------------------------------------------------------
__global__ __launch_bounds__(256)
void fold_kernel(float* __restrict__ out) {
    __shared__ float pr[N_NODES];
    __shared__ float Va[N_LEAVES];
    __shared__ float Vb[N_LEAVES / 2];

    const int row = blockIdx.x;
    const int tid = threadIdx.x;
    const float* p = &g_probs[(size_t)row * N_PAD];

    for (int i = tid; i < N_NODES; i += 256) pr[i] = p[i];
    for (int i = tid; i < N_LEAVES; i += 256) Va[i] = g_leaf_reward[i];
    __syncthreads();

    float* src = Va;
    float* dst = Vb;
    for (int k = 9; k >= 1; k--) {
        int cnt = 1 << k;
        int off = cnt - 1;
        for (int j = tid; j < cnt; j += 256) {
            float pp = pr[off + j];
            dst[j] = pp * src[2 * j] + (1.f - pp) * src[2 * j + 1];
        }
        __syncthreads();
        float* t = src; src = dst; dst = t;
    }
    if (tid == 0) {
        float pp = pr[0];
        out[row] = pp * src[0] + (1.f - pp) * src[1];
    }
}

// ---------------------------------------------------------------------------
// kernel_launch
//   inputs (metadata order): x, W, b, beta, leaf_dist, class_reward
//   output: loss [8192] float32
// ---------------------------------------------------------------------------
extern "C" void kernel_launch(void* const* d_in, const int* in_sizes, int n_in,
                              void* d_out, int out_size) {
    const float* x            = (const float*)d_in[0];
    const float* W            = (const float*)d_in[1];
    const float* b            = (const float*)d_in[2];
    const float* beta         = (const float*)d_in[3];
    const float* leaf_dist    = (const float*)d_in[4];
    const float* class_reward = (const float*)d_in[5];
    float* out = (float*)d_out;

    leaf_reward_kernel<<<(N_LEAVES + 127) / 128, 128>>>(leaf_dist, class_reward);

    dim3 grid(N_PAD / BN, M_BATCH / BM);   // 16 x 64
    gemm_sigmoid_kernel<<<grid, 256>>>(x, W, b, beta);

    fold_kernel<<<M_BATCH, 256>>>(out);
}